// round 8
// baseline (speedup 1.0000x reference)
#include <cuda_runtime.h>
#include <cuda_bf16.h>

// GraphGather / segment_sum:
//   out[b, :] = sum of feats[a, :] for membership[a] == b
// feats: [524288, 128] f32, membership: [524288] i32 (SORTED), out: [16384, 128] f32.
//
// R8 = R7 segsum with:
//  - PDL: zero-fill kernel triggers programmatic completion; segsum is
//    launched with ProgrammaticStreamSerialization, issues its membership
//    load + first 8 feature loads BEFORE cudaGridDependencySynchronize(),
//    and only syncs before the first possible red to out. Hides the
//    ~1.3us zero-fill under segsum's prologue.
//  - software-pipelined batches: load batch bt+1 while accumulating bt
//    (16 LDG.E.128 in flight at steady state).
//  - boundary flushes via red.global.add.v4.f32 (one 16B RMW per lane).

#define N_FEAT 128
#define FEAT4 (N_FEAT / 4)       // 32 float4 per row
#define ROWS_PER_WARP 32
#define TPB 256

__global__ __launch_bounds__(TPB)
void gg_zero4_kernel(float4* __restrict__ out, int n4) {
    int i = blockIdx.x * blockDim.x + threadIdx.x;
    if (i < n4) out[i] = make_float4(0.f, 0.f, 0.f, 0.f);
    cudaTriggerProgrammaticLaunchCompletion();
}

__device__ __forceinline__ void gg_flush(float* __restrict__ out,
                                         int seg, int lane, const float4& acc) {
    // byte offset = seg*512 + lane*16 -> 16B aligned.
    float* o = out + (size_t)seg * N_FEAT + lane * 4;
    asm volatile("red.global.add.v4.f32 [%0], {%1, %2, %3, %4};"
                 :: "l"(o), "f"(acc.x), "f"(acc.y), "f"(acc.z), "f"(acc.w)
                 : "memory");
}

__global__ __launch_bounds__(TPB)
void gg_segsum_kernel(const float4* __restrict__ feats,
                      const int* __restrict__ memb,
                      float* __restrict__ out,
                      int n_atoms) {
    const int warp_id = (blockIdx.x * TPB + threadIdx.x) >> 5;
    const int lane = threadIdx.x & 31;
    const unsigned FULL = 0xFFFFFFFFu;

    const int row0 = warp_id * ROWS_PER_WARP;
    if (row0 >= n_atoms) {
        cudaGridDependencySynchronize();
        return;
    }

    // One coalesced membership load for the warp's 32 rows (issued pre-sync).
    const int last = n_atoms - 1;
    int mrow = row0 + lane;
    int mlane = memb[mrow <= last ? mrow : last];

    const int nrows = (row0 + ROWS_PER_WARP <= n_atoms) ? ROWS_PER_WARP
                                                        : (n_atoms - row0);
    const float4* base = feats + (size_t)row0 * FEAT4 + lane;

    float4 acc = make_float4(0.f, 0.f, 0.f, 0.f);
    int cur = __shfl_sync(FULL, mlane, 0);

    if (nrows == ROWS_PER_WARP) {
        // Prefetch batch 0 (8 independent LDG.E.128) before waiting on the
        // zero-fill kernel: these read feats only, never out.
        float4 v[8];
        #pragma unroll
        for (int i = 0; i < 8; ++i)
            v[i] = __ldcs(base + (size_t)i * FEAT4);

        cudaGridDependencySynchronize();   // out is zeroed beyond this point

        #pragma unroll
        for (int bt = 0; bt < 4; ++bt) {
            // Issue next batch while accumulating the current one.
            float4 w[8];
            if (bt < 3) {
                #pragma unroll
                for (int i = 0; i < 8; ++i)
                    w[i] = __ldcs(base + (size_t)((bt + 1) * 8 + i) * FEAT4);
            }

            #pragma unroll
            for (int i = 0; i < 8; ++i) {
                int m = __shfl_sync(FULL, mlane, bt * 8 + i);
                if (m != cur) {            // rare: ~1 boundary / warp
                    gg_flush(out, cur, lane, acc);
                    acc = make_float4(0.f, 0.f, 0.f, 0.f);
                    cur = m;
                }
                acc.x += v[i].x; acc.y += v[i].y;
                acc.z += v[i].z; acc.w += v[i].w;
            }

            if (bt < 3) {
                #pragma unroll
                for (int i = 0; i < 8; ++i) v[i] = w[i];
            }
        }
    } else {
        cudaGridDependencySynchronize();
        for (int i = 0; i < nrows; ++i) {
            float4 v = __ldcs(base + (size_t)i * FEAT4);
            int m = __shfl_sync(FULL, mlane, i);
            if (m != cur) {
                gg_flush(out, cur, lane, acc);
                acc = make_float4(0.f, 0.f, 0.f, 0.f);
                cur = m;
            }
            acc.x += v.x; acc.y += v.y; acc.z += v.z; acc.w += v.w;
        }
    }

    gg_flush(out, cur, lane, acc);
}

extern "C" void kernel_launch(void* const* d_in, const int* in_sizes, int n_in,
                              void* d_out, int out_size) {
    const float4* feats = (const float4*)d_in[0];
    const int* memb = (const int*)d_in[1];
    float* out = (float*)d_out;

    const int n_atoms = in_sizes[1];      // 524288
    const int n4 = out_size / 4;          // 524288 float4

    // Primary: zero the poisoned output (triggers programmatic completion).
    gg_zero4_kernel<<<(n4 + TPB - 1) / TPB, TPB>>>((float4*)out, n4);

    // Secondary: segment-sum, launched with programmatic dependent launch so
    // its prologue (feats/memb loads) overlaps the zero-fill tail.
    const int n_warps = (n_atoms + ROWS_PER_WARP - 1) / ROWS_PER_WARP;
    const int blocks = (n_warps + (TPB / 32) - 1) / (TPB / 32);

    cudaLaunchConfig_t cfg = {};
    cfg.gridDim = dim3(blocks, 1, 1);
    cfg.blockDim = dim3(TPB, 1, 1);
    cfg.dynamicSmemBytes = 0;
    cfg.stream = 0;
    cudaLaunchAttribute attrs[1];
    attrs[0].id = cudaLaunchAttributeProgrammaticStreamSerialization;
    attrs[0].val.programmaticStreamSerializationAllowed = 1;
    cfg.attrs = attrs;
    cfg.numAttrs = 1;

    cudaLaunchKernelEx(&cfg, gg_segsum_kernel, feats, memb, out, n_atoms);
}

// round 9
// speedup vs baseline: 1.0095x; 1.0095x over previous
#include <cuda_runtime.h>
#include <cuda_bf16.h>

// GraphGather / segment_sum:
//   out[b, :] = sum of feats[a, :] for membership[a] == b
// feats: [524288, 128] f32, membership: [524288] i32 (SORTED), out: [16384, 128] f32.
//
// R9 = R6 segsum loop body (best: 44.2us, regs 54, DRAM 81%) + PDL zero-fill.
//  - NO double buffering (R8's reg blowup 54->86 killed occupancy/DRAM%).
//  - PDL: zero kernel triggers programmatic completion; segsum launched with
//    ProgrammaticStreamSerialization, prefetches membership + batch 0 of
//    feature loads (reads only) BEFORE cudaGridDependencySynchronize().
//  - 4 batches of 8 unconditional LDG.E.128 (MLP_p1 = 8), evict-first.
//  - boundary flushes via red.global.add.v4.f32 (one 16B RMW per lane).

#define N_FEAT 128
#define FEAT4 (N_FEAT / 4)       // 32 float4 per row
#define ROWS_PER_WARP 32
#define TPB 256

__global__ __launch_bounds__(TPB)
void gg_zero4_kernel(float4* __restrict__ out, int n4) {
    int i = blockIdx.x * blockDim.x + threadIdx.x;
    if (i < n4) out[i] = make_float4(0.f, 0.f, 0.f, 0.f);
    cudaTriggerProgrammaticLaunchCompletion();
}

__device__ __forceinline__ void gg_flush(float* __restrict__ out,
                                         int seg, int lane, const float4& acc) {
    // byte offset = seg*512 + lane*16 -> 16B aligned.
    float* o = out + (size_t)seg * N_FEAT + lane * 4;
    asm volatile("red.global.add.v4.f32 [%0], {%1, %2, %3, %4};"
                 :: "l"(o), "f"(acc.x), "f"(acc.y), "f"(acc.z), "f"(acc.w)
                 : "memory");
}

__global__ __launch_bounds__(TPB)
void gg_segsum_kernel(const float4* __restrict__ feats,
                      const int* __restrict__ memb,
                      float* __restrict__ out,
                      int n_atoms) {
    const int warp_id = (blockIdx.x * TPB + threadIdx.x) >> 5;
    const int lane = threadIdx.x & 31;
    const unsigned FULL = 0xFFFFFFFFu;

    const int row0 = warp_id * ROWS_PER_WARP;
    if (row0 >= n_atoms) {
        cudaGridDependencySynchronize();
        return;
    }

    // Prefetch (reads only; legal before the dependency sync):
    // membership for the warp's 32 rows, one coalesced load.
    const int last = n_atoms - 1;
    int mrow = row0 + lane;
    int mlane = memb[mrow <= last ? mrow : last];

    const int nrows = (row0 + ROWS_PER_WARP <= n_atoms) ? ROWS_PER_WARP
                                                        : (n_atoms - row0);
    const float4* base = feats + (size_t)row0 * FEAT4 + lane;

    float4 acc = make_float4(0.f, 0.f, 0.f, 0.f);
    int cur = __shfl_sync(FULL, mlane, 0);

    if (nrows == ROWS_PER_WARP) {
        // Batch 0 prefetch before waiting on the zero-fill kernel.
        float4 v[8];
        #pragma unroll
        for (int i = 0; i < 8; ++i)
            v[i] = __ldcs(base + (size_t)i * FEAT4);

        cudaGridDependencySynchronize();   // out is zeroed beyond this point

        #pragma unroll
        for (int bt = 0; bt < 4; ++bt) {
            if (bt > 0) {
                #pragma unroll
                for (int i = 0; i < 8; ++i)
                    v[i] = __ldcs(base + (size_t)(bt * 8 + i) * FEAT4);
            }

            #pragma unroll
            for (int i = 0; i < 8; ++i) {
                int m = __shfl_sync(FULL, mlane, bt * 8 + i);
                if (m != cur) {            // rare: ~1 boundary / warp
                    gg_flush(out, cur, lane, acc);
                    acc = make_float4(0.f, 0.f, 0.f, 0.f);
                    cur = m;
                }
                acc.x += v[i].x; acc.y += v[i].y;
                acc.z += v[i].z; acc.w += v[i].w;
            }
        }
    } else {
        cudaGridDependencySynchronize();
        for (int i = 0; i < nrows; ++i) {
            float4 v = __ldcs(base + (size_t)i * FEAT4);
            int m = __shfl_sync(FULL, mlane, i);
            if (m != cur) {
                gg_flush(out, cur, lane, acc);
                acc = make_float4(0.f, 0.f, 0.f, 0.f);
                cur = m;
            }
            acc.x += v.x; acc.y += v.y; acc.z += v.z; acc.w += v.w;
        }
    }

    gg_flush(out, cur, lane, acc);
}

extern "C" void kernel_launch(void* const* d_in, const int* in_sizes, int n_in,
                              void* d_out, int out_size) {
    const float4* feats = (const float4*)d_in[0];
    const int* memb = (const int*)d_in[1];
    float* out = (float*)d_out;

    const int n_atoms = in_sizes[1];      // 524288
    const int n4 = out_size / 4;          // 524288 float4

    // Primary: zero the poisoned output (triggers programmatic completion).
    gg_zero4_kernel<<<(n4 + TPB - 1) / TPB, TPB>>>((float4*)out, n4);

    // Secondary: segment-sum with programmatic dependent launch.
    const int n_warps = (n_atoms + ROWS_PER_WARP - 1) / ROWS_PER_WARP;
    const int blocks = (n_warps + (TPB / 32) - 1) / (TPB / 32);

    cudaLaunchConfig_t cfg = {};
    cfg.gridDim = dim3(blocks, 1, 1);
    cfg.blockDim = dim3(TPB, 1, 1);
    cfg.dynamicSmemBytes = 0;
    cfg.stream = 0;
    cudaLaunchAttribute attrs[1];
    attrs[0].id = cudaLaunchAttributeProgrammaticStreamSerialization;
    attrs[0].val.programmaticStreamSerializationAllowed = 1;
    cfg.attrs = attrs;
    cfg.numAttrs = 1;

    cudaLaunchKernelEx(&cfg, gg_segsum_kernel, feats, memb, out, n_atoms);
}